// round 5
// baseline (speedup 1.0000x reference)
#include <cuda_runtime.h>

// SoftDepthShader: softmax depth blend over K=50 slots per pixel.
// Sparsity insight: with GAMMA=1e-4, exp((zi-zmax)/GAMMA) underflows (ex2 arg
// < -126) unless zi is within ~0.0088 of the per-pixel max. With zi spread
// ~U[0,1], typically exactly ONE slot survives. So:
//   - dists is loaded ONLY for surviving slots (sparse, ~1 sector/pixel)
//   - the warp sum reduction collapses to a shfl from the surviving lane
// Dropped terms are <= 2^-126 vs denom >= 1e-10 -> rel effect <= ~1e-28.

#define KSLOTS 50
#define ZFAR 100.0f
#define INV_RANGE (1.0f / 99.0f)
#define EPSV 1e-10f
// exp(x/S) = exp2(x * log2(e)/S), SIGMA = GAMMA = 1e-4
#define SIG_L2E 1.4426950408889634e4f
#define GAM_L2E 1.4426950408889634e4f

__device__ __forceinline__ float fast_exp2(float x) {
    float y;
    asm("ex2.approx.ftz.f32 %0, %1;" : "=f"(y) : "f"(x));
    return y;
}

__global__ __launch_bounds__(256) void soft_depth_kernel(
    const float2* __restrict__ zbuf2,
    const int2*   __restrict__ p2f2,
    const float*  __restrict__ dists,
    float* __restrict__ out)
{
    const unsigned FULL = 0xFFFFFFFFu;
    const int warp_global = (blockIdx.x * blockDim.x + threadIdx.x) >> 5;
    const int lane = threadIdx.x & 31;

    // ---- coalesced loads: lane l<25 owns slots 2l, 2l+1 (row = 25 x 8B) ----
    float2 z2 = make_float2(ZFAR, ZFAR);
    int2   p2 = make_int2(-1, -1);
    if (lane < 25) {
        const int idx = warp_global * 25 + lane;
        z2 = __ldg(zbuf2 + idx);
        p2 = __ldg(p2f2  + idx);
    }
    const bool m0 = p2.x >= 0;
    const bool m1 = p2.y >= 0;

    const float zi0 = (ZFAR - z2.x) * INV_RANGE;   // in [0,1] when real
    const float zi1 = (ZFAR - z2.y) * INV_RANGE;

    // ---- warp max of masked zi (masked slots contribute 0, like reference) ----
    // values are >= 0 so int-compare on raw bits == float-compare
    float mx = fmaxf(m0 ? zi0 : 0.0f, m1 ? zi1 : 0.0f);
    int bits = __reduce_max_sync(FULL, __float_as_int(mx));
    const float zmax = fmaxf(__int_as_float(bits), EPSV);

    // ---- survivor test: only slots whose exp2 arg doesn't underflow ----
    const float arg0 = (zi0 - zmax) * GAM_L2E;
    const float arg1 = (zi1 - zmax) * GAM_L2E;
    const bool s0 = m0 && (arg0 > -126.0f);
    const bool s1 = m1 && (arg1 > -126.0f);

    float w = 0.0f, wz = 0.0f;
    const unsigned surv = __ballot_sync(FULL, s0 || s1);

    if (surv) {   // warp-uniform
        const int dbase = warp_global * KSLOTS + 2 * lane;
        if (s0) {
            float d  = __ldg(dists + dbase);
            // prob * exp((zi-zmax)/g) = exp2(arg0) / (1 + exp2(d/s*log2e))
            float wk = __fdividef(fast_exp2(arg0),
                                  1.0f + fast_exp2(d * SIG_L2E));
            w  = wk;
            wz = wk * z2.x;
        }
        if (s1) {
            float d  = __ldg(dists + dbase + 1);
            float wk = __fdividef(fast_exp2(arg1),
                                  1.0f + fast_exp2(d * SIG_L2E));
            w  += wk;
            wz  = fmaf(wk, z2.y, wz);
        }

        if (__popc(surv) == 1) {      // dominant case: one surviving lane
            const int src = __ffs(surv) - 1;
            w  = __shfl_sync(FULL, w,  src);
            wz = __shfl_sync(FULL, wz, src);
        } else {                      // rare: full butterfly
            #pragma unroll
            for (int off = 16; off > 0; off >>= 1) {
                w  += __shfl_xor_sync(FULL, w,  off);
                wz += __shfl_xor_sync(FULL, wz, off);
            }
        }
    }

    if (lane == 0) {
        float delta = fmaxf(fast_exp2((EPSV - zmax) * GAM_L2E), EPSV);
        // BG_BLUE = 1.0 -> numerator + delta
        out[warp_global] = (wz + delta) * __fdividef(1.0f, w + delta);
    }
}

extern "C" void kernel_launch(void* const* d_in, const int* in_sizes, int n_in,
                              void* d_out, int out_size)
{
    const float2* zbuf2  = (const float2*)d_in[0];
    const float*  dists  = (const float*)d_in[1];
    const int2*   p2f2   = (const int2*)d_in[2];
    float*        out    = (float*)d_out;

    const int npix = in_sizes[0] / KSLOTS;    // 524288
    const int threads = 256;                  // 8 warps = 8 pixels / block
    const int blocks = npix / (threads / 32); // 65536

    soft_depth_kernel<<<blocks, threads>>>(zbuf2, p2f2, dists, out);
}

// round 6
// speedup vs baseline: 1.2658x; 1.2658x over previous
#include <cuda_runtime.h>

// SoftDepthShader: softmax depth blend over K=50 slots per pixel.
//
// R5 design:
//  - ALL THREE arrays loaded bulk + coalesced up front (3 independent LDG.64
//    per lane -> max MLP; R4 showed a dependent post-reduction load is fatal).
//  - work in exp2-argument space: a = (ZFAR - z) * log2(e)/(GAMMA*(ZFAR-ZNEAR));
//    max/survivor-test/exp args are then single subtracts.
//  - survivors (a > amax - 126, i.e. exp2 doesn't flush to zero) are ~1.4 per
//    pixel; weight math branch-gated, reduction is one shfl from the surviving
//    lane in the dominant popc==1 case. Dropped terms <= 2^-126 vs denom
//    >= 1e-10 -> immaterial at rel_err 1e-3.

#define KSLOTS 50
#define ZFAR 100.0f
#define EPSV 1e-10f
#define L2E 1.4426950408889634f
// exp((zi - zm)/GAMMA) = exp2( (a - am) ) with a = (ZFAR-z) * AC
#define AC (L2E * 1.0e4f / 99.0f)          // 145.72677...
#define SIG_L2E (L2E * 1.0e4f)             // dists sigmoid scale
#define EPS_A (EPSV * L2E * 1.0e4f)        // EPS in a-space

__device__ __forceinline__ float fast_exp2(float x) {
    float y;
    asm("ex2.approx.ftz.f32 %0, %1;" : "=f"(y) : "f"(x));
    return y;
}

__global__ __launch_bounds__(256) void soft_depth_kernel(
    const float2* __restrict__ zbuf2,
    const float2* __restrict__ dists2,
    const int2*   __restrict__ p2f2,
    float* __restrict__ out)
{
    const unsigned FULL = 0xFFFFFFFFu;
    const int warp_global = (blockIdx.x * blockDim.x + threadIdx.x) >> 5;
    const int lane = threadIdx.x & 31;

    // ---- bulk coalesced loads: lane l<25 owns slots 2l,2l+1 (row=25 x 8B) ----
    float2 z2 = make_float2(ZFAR, ZFAR);
    float2 d2 = make_float2(0.f, 0.f);
    int2   p2 = make_int2(-1, -1);
    if (lane < 25) {
        const int idx = warp_global * 25 + lane;
        z2 = __ldg(zbuf2  + idx);
        d2 = __ldg(dists2 + idx);
        p2 = __ldg(p2f2   + idx);
    }
    const bool m0 = p2.x >= 0;
    const bool m1 = p2.y >= 0;

    // a = (ZFAR - z) * AC  (>= 0); masked slots contribute 0 (like reference)
    const float a0 = m0 ? (ZFAR - z2.x) * AC : 0.f;
    const float a1 = m1 ? (ZFAR - z2.y) * AC : 0.f;

    // ---- warp max of a (a >= 0 so int-compare on raw bits == float order) ----
    int bits = __reduce_max_sync(FULL, __float_as_int(fmaxf(a0, a1)));
    const float amax = fmaxf(__int_as_float(bits), EPS_A);

    // ---- survivor test: exp2(a - amax) nonzero only if a - amax > -126 ----
    const float lim = amax - 126.0f;
    const bool s0 = m0 && (a0 > lim);
    const bool s1 = m1 && (a1 > lim);

    float w = 0.f, wz = 0.f;
    const unsigned surv = __ballot_sync(FULL, s0 || s1);

    if (s0 || s1) {
        if (s0) {
            float wk = __fdividef(fast_exp2(a0 - amax),
                                  1.0f + fast_exp2(d2.x * SIG_L2E));
            w  = wk;
            wz = wk * z2.x;
        }
        if (s1) {
            float wk = __fdividef(fast_exp2(a1 - amax),
                                  1.0f + fast_exp2(d2.y * SIG_L2E));
            w  += wk;
            wz  = fmaf(wk, z2.y, wz);
        }
    }

    if (__popc(surv) == 1) {           // dominant: one surviving lane
        const int src = __ffs(surv) - 1;
        w  = __shfl_sync(FULL, w,  src);
        wz = __shfl_sync(FULL, wz, src);
    } else {                           // rare: full butterfly
        #pragma unroll
        for (int off = 16; off > 0; off >>= 1) {
            w  += __shfl_xor_sync(FULL, w,  off);
            wz += __shfl_xor_sync(FULL, wz, off);
        }
    }

    if (lane == 0) {
        float delta = fmaxf(fast_exp2(EPS_A - amax), EPSV);
        // BG_BLUE = 1.0 -> numerator + delta
        out[warp_global] = (wz + delta) * __fdividef(1.0f, w + delta);
    }
}

extern "C" void kernel_launch(void* const* d_in, const int* in_sizes, int n_in,
                              void* d_out, int out_size)
{
    const float2* zbuf2  = (const float2*)d_in[0];
    const float2* dists2 = (const float2*)d_in[1];
    const int2*   p2f2   = (const int2*)d_in[2];
    float*        out    = (float*)d_out;

    const int npix = in_sizes[0] / KSLOTS;    // 524288
    const int threads = 256;                  // 8 warps = 8 pixels / block
    const int blocks = npix / (threads / 32); // 65536

    soft_depth_kernel<<<blocks, threads>>>(zbuf2, dists2, p2f2, out);
}

// round 7
// speedup vs baseline: 1.4735x; 1.1641x over previous
#include <cuda_runtime.h>

// SoftDepthShader: softmax depth blend over K=50 slots per pixel.
//
// R6: latency-bound fix — 2 pixels per warp via float4 loads.
//   Two rows = 100 floats = 400 B = 25 float4, 16B-aligned for every warp.
//   Lane l<25 loads one float4/int4 per array -> 3 LDG.128, 1200 B in flight
//   per warp (2x R5) at unchanged occupancy => doubles Little's-law BW.
//   Epilogue: work in exp2-arg space a=(ZFAR-z)*AC, two REDUX maxes, survivor
//   gating (exp2 underflow: only slots within 126 of the max contribute,
//   ~1.4/pixel), ballot+shfl reduction, lane0 writes float2.

#define KSLOTS 50
#define ZFAR 100.0f
#define EPSV 1e-10f
#define L2E 1.4426950408889634f
#define AC (L2E * 1.0e4f / 99.0f)      // exp((zi-zm)/G) = exp2(a - amax)
#define NAC (-(L2E * 1.0e4f / 99.0f))
#define ZAC (ZFAR * L2E * 1.0e4f / 99.0f)
#define SIG_L2E (L2E * 1.0e4f)
#define EPS_A (EPSV * L2E * 1.0e4f)

__device__ __forceinline__ float fast_exp2(float x) {
    float y;
    asm("ex2.approx.ftz.f32 %0, %1;" : "=f"(y) : "f"(x));
    return y;
}

__global__ __launch_bounds__(256) void soft_depth_kernel(
    const float4* __restrict__ zbuf4,
    const float4* __restrict__ dists4,
    const int4*   __restrict__ p2f4,
    float2* __restrict__ out)
{
    const unsigned FULL = 0xFFFFFFFFu;
    const int w = (blockIdx.x * blockDim.x + threadIdx.x) >> 5;  // warp id = pixel pair
    const int lane = threadIdx.x & 31;

    // ---- bulk loads: lane l<25 owns elements 4l..4l+3 of the 100-elem pair ----
    float4 z4 = make_float4(ZFAR, ZFAR, ZFAR, ZFAR);
    float4 d4 = make_float4(0.f, 0.f, 0.f, 0.f);
    int4   p4 = make_int4(-1, -1, -1, -1);
    if (lane < 25) {
        const int idx = w * 25 + lane;
        z4 = __ldg(zbuf4  + idx);
        d4 = __ldg(dists4 + idx);
        p4 = __ldg(p2f4   + idx);
    }
    const float* zf = &z4.x;
    const float* df = &d4.x;
    const int*   pf = &p4.x;
    const int ebase = 4 * lane;          // element index within the 100

    float a[4];
    bool  m[4];
    float mx0 = 0.f, mx1 = 0.f;          // per-lane max per pixel (masked -> 0)
    #pragma unroll
    for (int j = 0; j < 4; j++) {
        m[j] = pf[j] >= 0;
        a[j] = m[j] ? fmaf(zf[j], NAC, ZAC) : 0.f;   // (ZFAR - z) * AC, >= 0
        if (ebase + j < KSLOTS) mx0 = fmaxf(mx0, a[j]);
        else                    mx1 = fmaxf(mx1, a[j]);
    }

    // ---- warp maxes (values >= 0: int order == float order) ----
    const float amax0 = fmaxf(__int_as_float(
        __reduce_max_sync(FULL, __float_as_int(mx0))), EPS_A);
    const float amax1 = fmaxf(__int_as_float(
        __reduce_max_sync(FULL, __float_as_int(mx1))), EPS_A);
    const float lim0 = amax0 - 126.0f;
    const float lim1 = amax1 - 126.0f;

    // ---- survivor-gated weights ----
    float w0 = 0.f, wz0 = 0.f, w1 = 0.f, wz1 = 0.f;
    bool any0 = false, any1 = false;
    #pragma unroll
    for (int j = 0; j < 4; j++) {
        const bool isp0 = (ebase + j) < KSLOTS;
        const float lim = isp0 ? lim0 : lim1;
        if (m[j] && a[j] > lim) {
            const float am = isp0 ? amax0 : amax1;
            float wk = __fdividef(fast_exp2(a[j] - am),
                                  1.0f + fast_exp2(df[j] * SIG_L2E));
            if (isp0) { w0 += wk; wz0 = fmaf(wk, zf[j], wz0); any0 = true; }
            else      { w1 += wk; wz1 = fmaf(wk, zf[j], wz1); any1 = true; }
        }
    }

    const unsigned b0 = __ballot_sync(FULL, any0);
    const unsigned b1 = __ballot_sync(FULL, any1);

    if (__popc(b0) <= 1 && __popc(b1) <= 1) {   // dominant: <=1 lane per pixel
        const int s0 = b0 ? (__ffs(b0) - 1) : 0;
        const int s1 = b1 ? (__ffs(b1) - 1) : 0;
        w0  = __shfl_sync(FULL, w0,  s0);
        wz0 = __shfl_sync(FULL, wz0, s0);
        w1  = __shfl_sync(FULL, w1,  s1);
        wz1 = __shfl_sync(FULL, wz1, s1);
    } else {                                    // rare: full butterfly
        #pragma unroll
        for (int off = 16; off > 0; off >>= 1) {
            w0  += __shfl_xor_sync(FULL, w0,  off);
            wz0 += __shfl_xor_sync(FULL, wz0, off);
            w1  += __shfl_xor_sync(FULL, w1,  off);
            wz1 += __shfl_xor_sync(FULL, wz1, off);
        }
    }

    if (lane == 0) {
        const float delta0 = fmaxf(fast_exp2(EPS_A - amax0), EPSV);
        const float delta1 = fmaxf(fast_exp2(EPS_A - amax1), EPSV);
        float2 o;
        o.x = (wz0 + delta0) * __fdividef(1.0f, w0 + delta0);  // BG_BLUE = 1
        o.y = (wz1 + delta1) * __fdividef(1.0f, w1 + delta1);
        out[w] = o;
    }
}

extern "C" void kernel_launch(void* const* d_in, const int* in_sizes, int n_in,
                              void* d_out, int out_size)
{
    const float4* zbuf4  = (const float4*)d_in[0];
    const float4* dists4 = (const float4*)d_in[1];
    const int4*   p2f4   = (const int4*)d_in[2];
    float2*       out    = (float2*)d_out;

    const int npix  = in_sizes[0] / KSLOTS;   // 524288
    const int pairs = npix / 2;               // 262144 warps
    const int threads = 256;                  // 8 warps/block
    const int blocks = pairs / (threads / 32);// 32768

    soft_depth_kernel<<<blocks, threads>>>(zbuf4, dists4, p2f4, out);
}

// round 8
// speedup vs baseline: 1.6098x; 1.0925x over previous
#include <cuda_runtime.h>

// SoftDepthShader: softmax depth blend over K=50 slots per pixel.
//
// R7: 4 pixels per warp via 2 load-sets of 25 float4 per array
//     (6 LDG.128 / warp -> 2400 B in flight, 2x R6) + leaner epilogue:
//     per-lane-group pixel routing (elements {0,1} and {2,3} of a lane's
//     float4 belong to lane-constant pixels, boundary at lane 12),
//     warp-uniform ballot gather-loop instead of butterfly reductions.
// Sparsity: exp2(a - amax) flushes to 0 unless a within 126 of the max
// (~1.4 survivors/pixel); dropped terms <= 2^-126 vs denom >= 1e-10.

#define KSLOTS 50
#define ZFAR 100.0f
#define EPSV 1e-10f
#define L2E 1.4426950408889634f
#define NAC (-(L2E * 1.0e4f / 99.0f))     // a = (ZFAR - z)*AC = fma(z, NAC, ZAC)
#define ZAC (ZFAR * L2E * 1.0e4f / 99.0f)
#define SIG_L2E (L2E * 1.0e4f)
#define EPS_A (EPSV * L2E * 1.0e4f)

__device__ __forceinline__ float fast_exp2(float x) {
    float y;
    asm("ex2.approx.ftz.f32 %0, %1;" : "=f"(y) : "f"(x));
    return y;
}

// Process one load-set (2 pixels, 100 elems in 25 float4s held by lanes 0-24).
// selA: this lane's elements {0,1} belong to local pixel 0 (lane <= 12)
// selB: this lane's elements {2,3} belong to local pixel 0 (lane <  12)
__device__ __forceinline__ void blend_pair(
    const float4& z4, const float4& d4, const int4& p4,
    bool selA, bool selB, unsigned FULL,
    float& out0, float& out1)
{
    const float* zf = &z4.x;
    const float* df = &d4.x;
    const int*   pf = &p4.x;

    float a[4];
    #pragma unroll
    for (int j = 0; j < 4; j++)
        a[j] = (pf[j] >= 0) ? fmaf(zf[j], NAC, ZAC) : 0.f;   // >= 0

    const float mA = fmaxf(a[0], a[1]);
    const float mB = fmaxf(a[2], a[3]);
    const float mx0 = fmaxf(selA ? mA : 0.f, selB ? mB : 0.f);
    const float mx1 = fmaxf(selA ? 0.f : mA, selB ? 0.f : mB);

    // values >= 0 so int order == float order
    const float amax0 = fmaxf(__int_as_float(
        __reduce_max_sync(FULL, __float_as_int(mx0))), EPS_A);
    const float amax1 = fmaxf(__int_as_float(
        __reduce_max_sync(FULL, __float_as_int(mx1))), EPS_A);

    const float amA = selA ? amax0 : amax1;
    const float amB = selB ? amax0 : amax1;
    const float limA = amA - 126.0f;
    const float limB = amB - 126.0f;

    // survivor-gated weights, accumulated per group
    float wA = 0.f, wzA = 0.f, wB = 0.f, wzB = 0.f;
    #pragma unroll
    for (int j = 0; j < 2; j++) {
        if (a[j] > limA && pf[j] >= 0) {
            float wk = __fdividef(fast_exp2(a[j] - amA),
                                  1.0f + fast_exp2(df[j] * SIG_L2E));
            wA += wk; wzA = fmaf(wk, zf[j], wzA);
        }
    }
    #pragma unroll
    for (int j = 2; j < 4; j++) {
        if (a[j] > limB && pf[j] >= 0) {
            float wk = __fdividef(fast_exp2(a[j] - amB),
                                  1.0f + fast_exp2(df[j] * SIG_L2E));
            wB += wk; wzB = fmaf(wk, zf[j], wzB);
        }
    }

    // route group sums to pixels (lane-constant selects)
    const float w0l  = (selA ? wA  : 0.f) + (selB ? wB  : 0.f);
    const float wz0l = (selA ? wzA : 0.f) + (selB ? wzB : 0.f);
    const float w1l  = (selA ? 0.f : wA)  + (selB ? 0.f : wB);
    const float wz1l = (selA ? 0.f : wzA) + (selB ? 0.f : wzB);

    // warp-uniform gather over surviving lanes (typically 1-2 per pixel)
    unsigned b0 = __ballot_sync(FULL, w0l > 0.f);
    unsigned b1 = __ballot_sync(FULL, w1l > 0.f);

    float w0 = 0.f, wz0 = 0.f, w1 = 0.f, wz1 = 0.f;
    while (b0) {
        const int src = __ffs(b0) - 1;  b0 &= b0 - 1;
        w0  += __shfl_sync(FULL, w0l,  src);
        wz0 += __shfl_sync(FULL, wz0l, src);
    }
    while (b1) {
        const int src = __ffs(b1) - 1;  b1 &= b1 - 1;
        w1  += __shfl_sync(FULL, w1l,  src);
        wz1 += __shfl_sync(FULL, wz1l, src);
    }

    const float delta0 = fmaxf(fast_exp2(EPS_A - amax0), EPSV);
    const float delta1 = fmaxf(fast_exp2(EPS_A - amax1), EPSV);
    out0 = (wz0 + delta0) * __fdividef(1.0f, w0 + delta0);   // BG_BLUE = 1
    out1 = (wz1 + delta1) * __fdividef(1.0f, w1 + delta1);
}

__global__ __launch_bounds__(256) void soft_depth_kernel(
    const float4* __restrict__ zbuf4,
    const float4* __restrict__ dists4,
    const int4*   __restrict__ p2f4,
    float4* __restrict__ out4)
{
    const unsigned FULL = 0xFFFFFFFFu;
    const int w = (blockIdx.x * blockDim.x + threadIdx.x) >> 5;  // warp = 4 pixels
    const int lane = threadIdx.x & 31;

    // ---- all 6 independent LDG.128 issued up front (max MLP) ----
    float4 z4a = make_float4(ZFAR, ZFAR, ZFAR, ZFAR), z4b = z4a;
    float4 d4a = make_float4(0.f, 0.f, 0.f, 0.f),     d4b = d4a;
    int4   p4a = make_int4(-1, -1, -1, -1),           p4b = p4a;
    if (lane < 25) {
        const int i0 = w * 50 + lane;        // float4 index, set A (pixels 0,1)
        const int i1 = i0 + 25;              // set B (pixels 2,3)
        z4a = __ldg(zbuf4  + i0);
        z4b = __ldg(zbuf4  + i1);
        d4a = __ldg(dists4 + i0);
        d4b = __ldg(dists4 + i1);
        p4a = __ldg(p2f4   + i0);
        p4b = __ldg(p2f4   + i1);
    }

    const bool selA = (lane <= 12);   // elements {0,1} -> local pixel 0
    const bool selB = (lane <  12);   // elements {2,3} -> local pixel 0

    float4 o;
    blend_pair(z4a, d4a, p4a, selA, selB, FULL, o.x, o.y);
    blend_pair(z4b, d4b, p4b, selA, selB, FULL, o.z, o.w);

    if (lane == 0) out4[w] = o;
}

extern "C" void kernel_launch(void* const* d_in, const int* in_sizes, int n_in,
                              void* d_out, int out_size)
{
    const float4* zbuf4  = (const float4*)d_in[0];
    const float4* dists4 = (const float4*)d_in[1];
    const int4*   p2f4   = (const int4*)d_in[2];
    float4*       out4   = (float4*)d_out;

    const int npix  = in_sizes[0] / KSLOTS;   // 524288
    const int quads = npix / 4;               // 131072 warps
    const int threads = 256;                  // 8 warps/block
    const int blocks = quads / (threads / 32);// 16384

    soft_depth_kernel<<<blocks, threads>>>(zbuf4, dists4, p2f4, out4);
}

// round 10
// speedup vs baseline: 1.6208x; 1.0069x over previous
#include <cuda_runtime.h>

// SoftDepthShader: softmax depth blend over K=50 slots per pixel.
//
// R8: R7 memory shape (4 pixels/warp, 6x LDG.128 -> 2400 B in flight) with a
// branchless epilogue:
//  - group-gated survivor math (test group max vs underflow cutoff first)
//  - 2-slot branchless ballot gather per pixel (ffs + clamp-to-lane31, whose
//    weight is always 0), exact residual loop behind ONE rare branch per pair
// Sparsity: exp2(a - amax) flushes to 0 unless a within 126 of amax (same
// cutoff where the reference's f32 exp underflows), ~1.4 survivors/pixel.

#define KSLOTS 50
#define ZFAR 100.0f
#define EPSV 1e-10f
#define L2E 1.4426950408889634f
#define NAC (-(L2E * 1.0e4f / 99.0f))     // a = (ZFAR - z)*AC = fma(z, NAC, ZAC)
#define ZAC (ZFAR * L2E * 1.0e4f / 99.0f)
#define SIG_L2E (L2E * 1.0e4f)
#define EPS_A (EPSV * L2E * 1.0e4f)

__device__ __forceinline__ float fast_exp2(float x) {
    float y;
    asm("ex2.approx.ftz.f32 %0, %1;" : "=f"(y) : "f"(x));
    return y;
}

// One load-set = 2 pixels = 100 elems in 25 float4s (lanes 0-24).
// selA: lane's elements {0,1} belong to local pixel 0 (lane <= 12)
// selB: lane's elements {2,3} belong to local pixel 0 (lane <  12)
__device__ __forceinline__ void blend_pair(
    const float4& z4, const float4& d4, const int4& p4,
    bool selA, bool selB, unsigned FULL,
    float& out0, float& out1)
{
    // masked slots contribute a = 0 (reference: z_inv * mask)
    const float a0 = (p4.x >= 0) ? fmaf(z4.x, NAC, ZAC) : 0.f;
    const float a1 = (p4.y >= 0) ? fmaf(z4.y, NAC, ZAC) : 0.f;
    const float a2 = (p4.z >= 0) ? fmaf(z4.z, NAC, ZAC) : 0.f;
    const float a3 = (p4.w >= 0) ? fmaf(z4.w, NAC, ZAC) : 0.f;

    const float mA = fmaxf(a0, a1);
    const float mB = fmaxf(a2, a3);

    // per-pixel warp max (values >= 0: int order == float order)
    const float mx0 = fmaxf(selA ? mA : 0.f, selB ? mB : 0.f);
    const float mx1 = fmaxf(selA ? 0.f : mA, selB ? 0.f : mB);
    const float amax0 = fmaxf(__int_as_float(
        __reduce_max_sync(FULL, __float_as_int(mx0))), EPS_A);
    const float amax1 = fmaxf(__int_as_float(
        __reduce_max_sync(FULL, __float_as_int(mx1))), EPS_A);

    const float amA = selA ? amax0 : amax1;
    const float amB = selB ? amax0 : amax1;
    const float cA  = amA - 126.0f;       // exp2 underflow cutoff
    const float cB  = amB - 126.0f;

    // survivor-gated weights, group-level gate first (~65% skip)
    float wA = 0.f, wzA = 0.f, wB = 0.f, wzB = 0.f;
    if (mA > cA) {
        if (a0 > cA && p4.x >= 0) {
            float wk = __fdividef(fast_exp2(a0 - amA),
                                  1.0f + fast_exp2(d4.x * SIG_L2E));
            wA += wk; wzA = fmaf(wk, z4.x, wzA);
        }
        if (a1 > cA && p4.y >= 0) {
            float wk = __fdividef(fast_exp2(a1 - amA),
                                  1.0f + fast_exp2(d4.y * SIG_L2E));
            wA += wk; wzA = fmaf(wk, z4.y, wzA);
        }
    }
    if (mB > cB) {
        if (a2 > cB && p4.z >= 0) {
            float wk = __fdividef(fast_exp2(a2 - amB),
                                  1.0f + fast_exp2(d4.z * SIG_L2E));
            wB += wk; wzB = fmaf(wk, z4.z, wzB);
        }
        if (a3 > cB && p4.w >= 0) {
            float wk = __fdividef(fast_exp2(a3 - amB),
                                  1.0f + fast_exp2(d4.w * SIG_L2E));
            wB += wk; wzB = fmaf(wk, z4.w, wzB);
        }
    }

    // route group sums to pixels (lane-constant selects)
    const float w0l  = (selA ? wA  : 0.f) + (selB ? wB  : 0.f);
    const float wz0l = (selA ? wzA : 0.f) + (selB ? wzB : 0.f);
    const float w1l  = (selA ? 0.f : wA)  + (selB ? 0.f : wB);
    const float wz1l = (selA ? 0.f : wzA) + (selB ? 0.f : wzB);

    // ---- branchless 2-slot gather (lanes >= 25 always carry 0) ----
    const unsigned b0 = __ballot_sync(FULL, w0l != 0.f);
    const unsigned b1 = __ballot_sync(FULL, w1l != 0.f);
    const unsigned r0 = b0 & (b0 - 1);
    const unsigned r1 = b1 & (b1 - 1);

    int s0a = __ffs(b0) - 1;  s0a = (s0a < 0) ? 31 : s0a;
    int s0b = __ffs(r0) - 1;  s0b = (s0b < 0) ? 31 : s0b;
    int s1a = __ffs(b1) - 1;  s1a = (s1a < 0) ? 31 : s1a;
    int s1b = __ffs(r1) - 1;  s1b = (s1b < 0) ? 31 : s1b;

    float w0  = __shfl_sync(FULL, w0l,  s0a) + __shfl_sync(FULL, w0l,  s0b);
    float wz0 = __shfl_sync(FULL, wz0l, s0a) + __shfl_sync(FULL, wz0l, s0b);
    float w1  = __shfl_sync(FULL, w1l,  s1a) + __shfl_sync(FULL, w1l,  s1b);
    float wz1 = __shfl_sync(FULL, wz1l, s1a) + __shfl_sync(FULL, wz1l, s1b);

    // exact residual for >= 3 surviving lanes (warp-uniform, rare)
    unsigned rem0 = r0 & (r0 - 1);
    unsigned rem1 = r1 & (r1 - 1);
    if (rem0 | rem1) {
        while (rem0) {
            const int s = __ffs(rem0) - 1;  rem0 &= rem0 - 1;
            w0  += __shfl_sync(FULL, w0l,  s);
            wz0 += __shfl_sync(FULL, wz0l, s);
        }
        while (rem1) {
            const int s = __ffs(rem1) - 1;  rem1 &= rem1 - 1;
            w1  += __shfl_sync(FULL, w1l,  s);
            wz1 += __shfl_sync(FULL, wz1l, s);
        }
    }

    const float delta0 = fmaxf(fast_exp2(EPS_A - amax0), EPSV);
    const float delta1 = fmaxf(fast_exp2(EPS_A - amax1), EPSV);
    out0 = (wz0 + delta0) * __fdividef(1.0f, w0 + delta0);   // BG_BLUE = 1
    out1 = (wz1 + delta1) * __fdividef(1.0f, w1 + delta1);
}

__global__ __launch_bounds__(256) void soft_depth_kernel(
    const float4* __restrict__ zbuf4,
    const float4* __restrict__ dists4,
    const int4*   __restrict__ p2f4,
    float4* __restrict__ out4)
{
    const unsigned FULL = 0xFFFFFFFFu;
    const int w = (blockIdx.x * blockDim.x + threadIdx.x) >> 5;  // warp = 4 pixels
    const int lane = threadIdx.x & 31;

    // ---- all 6 independent LDG.128 issued up front (max MLP) ----
    float4 z4a = make_float4(ZFAR, ZFAR, ZFAR, ZFAR), z4b = z4a;
    float4 d4a = make_float4(0.f, 0.f, 0.f, 0.f),     d4b = d4a;
    int4   p4a = make_int4(-1, -1, -1, -1),           p4b = p4a;
    if (lane < 25) {
        const int i0 = w * 50 + lane;        // set A (pixels 0,1)
        const int i1 = i0 + 25;              // set B (pixels 2,3)
        z4a = __ldg(zbuf4  + i0);
        z4b = __ldg(zbuf4  + i1);
        d4a = __ldg(dists4 + i0);
        d4b = __ldg(dists4 + i1);
        p4a = __ldg(p2f4   + i0);
        p4b = __ldg(p2f4   + i1);
    }

    const bool selA = (lane <= 12);   // elements {0,1} -> local pixel 0
    const bool selB = (lane <  12);   // elements {2,3} -> local pixel 0

    float4 o;
    blend_pair(z4a, d4a, p4a, selA, selB, FULL, o.x, o.y);
    blend_pair(z4b, d4b, p4b, selA, selB, FULL, o.z, o.w);

    if (lane == 0) out4[w] = o;
}

extern "C" void kernel_launch(void* const* d_in, const int* in_sizes, int n_in,
                              void* d_out, int out_size)
{
    const float4* zbuf4  = (const float4*)d_in[0];
    const float4* dists4 = (const float4*)d_in[1];
    const int4*   p2f4   = (const int4*)d_in[2];
    float4*       out4   = (float4*)d_out;

    const int npix  = in_sizes[0] / KSLOTS;   // 524288
    const int quads = npix / 4;               // 131072 warps
    const int threads = 256;                  // 8 warps/block
    const int blocks = quads / (threads / 32);// 16384

    soft_depth_kernel<<<blocks, threads>>>(zbuf4, dists4, p2f4, out4);
}